// round 1
// baseline (speedup 1.0000x reference)
#include <cuda_runtime.h>
#include <cuda_bf16.h>

// Problem constants (fixed shapes from reference setup_inputs)
constexpr int NN  = 100000;   // nodes
constexpr int EE  = 1600000;  // edges
constexpr int FIN = 128;
constexpr int HID = 128;
constexpr int OUTC = 64;

// ---------------- scratch (static device globals; allocation-free) ----------
__device__ float    g_h1[NN * HID];    // x @ W_src1
__device__ float    g_agg1[NN * HID];  // layer1 aggregated (then bias+relu in place)
__device__ float    g_h2[NN * OUTC];   // relu(agg1) @ W_src2
__device__ float    g_asrc[NN];
__device__ float    g_adst[NN];
__device__ unsigned g_m[NN];           // encoded float max
__device__ float    g_denom[NN];
__device__ float    g_e[EE];           // edge scratch: e -> ee
__device__ float    g_wa[2 * 128];     // [wa_src | wa_dst] for current layer

// monotonic float<->uint encoding for atomicMax
__device__ __forceinline__ unsigned enc_f(float f) {
    unsigned u = __float_as_uint(f);
    return (u & 0x80000000u) ? ~u : (u | 0x80000000u);
}
__device__ __forceinline__ float dec_f(unsigned u) {
    return (u & 0x80000000u) ? __uint_as_float(u & 0x7fffffffu)
                             : __uint_as_float(~u);
}

// ---------------- wa = W @ att (both src and dst), 128 outputs -------------
__global__ void k_wa(const float* __restrict__ Wsrc, const float* __restrict__ asrc,
                     const float* __restrict__ Wdst, const float* __restrict__ adst,
                     int cols) {
    int k = threadIdx.x;  // 128 threads, one per input-feature row of W
    float s1 = 0.f, s2 = 0.f;
    for (int j = 0; j < cols; j++) {
        s1 += Wsrc[k * cols + j] * asrc[j];
        s2 += Wdst[k * cols + j] * adst[j];
    }
    g_wa[k]       = s1;
    g_wa[128 + k] = s2;
}

// ---------------- GEMM: Y[N,COLS] = X[N,128] @ W[128,COLS] ------------------
// Also computes per-row dots with g_wa (a_src / a_dst) from the smem tile.
template <int COLS>
__global__ __launch_bounds__(COLS) void k_gemm(const float* __restrict__ X,
                                               const float* __restrict__ W,
                                               float* __restrict__ Y) {
    constexpr int RPB = 32;   // rows per block
    constexpr int KP  = 36;   // padded row stride for transposed tile
    __shared__ float xs[128 * KP];  // xs[k*KP + r]

    const int row0 = blockIdx.x * RPB;
    const int t = threadIdx.x;

    // load + transpose tile (coalesced gmem reads)
    for (int idx = t; idx < RPB * 128; idx += COLS) {
        int r = idx >> 7;
        int k = idx & 127;
        xs[k * KP + r] = X[(row0 + r) * 128 + k];
    }
    __syncthreads();

    float acc[RPB];
#pragma unroll
    for (int r = 0; r < RPB; r++) acc[r] = 0.f;

#pragma unroll 4
    for (int k = 0; k < 128; k++) {
        float w = W[k * COLS + t];
        const float4* xp = (const float4*)&xs[k * KP];
#pragma unroll
        for (int rq = 0; rq < RPB / 4; rq++) {
            float4 xv = xp[rq];
            acc[rq * 4 + 0] += xv.x * w;
            acc[rq * 4 + 1] += xv.y * w;
            acc[rq * 4 + 2] += xv.z * w;
            acc[rq * 4 + 3] += xv.w * w;
        }
    }
#pragma unroll
    for (int r = 0; r < RPB; r++) Y[(row0 + r) * COLS + t] = acc[r];

    // per-row attention scalars from the same tile
    constexpr int TPR = COLS / 32;      // threads per row (4 or 2)
    constexpr int KSEG = 128 / TPR;
    int r = t / TPR, q = t % TPR;
    int k0 = q * KSEG;
    float s1 = 0.f, s2 = 0.f;
    for (int k = k0; k < k0 + KSEG; k++) {
        float xv = xs[k * KP + r];
        s1 += xv * g_wa[k];
        s2 += xv * g_wa[128 + k];
    }
#pragma unroll
    for (int off = TPR / 2; off > 0; off >>= 1) {
        s1 += __shfl_xor_sync(0xffffffffu, s1, off);
        s2 += __shfl_xor_sync(0xffffffffu, s2, off);
    }
    if (q == 0) {
        g_asrc[row0 + r] = s1;
        g_adst[row0 + r] = s2;
    }
}

// ---------------- init: zero accumulator, reset m/denom ---------------------
__global__ void k_init(float* __restrict__ agg, int n_agg) {
    int i = blockIdx.x * blockDim.x + threadIdx.x;
    if (i < n_agg) agg[i] = 0.f;
    if (i < NN) {
        g_m[i] = 0u;         // enc of -inf (smallest)
        g_denom[i] = 0.f;
    }
}

// ---------------- edge pass A: logits + segment max -------------------------
__global__ void k_edgeA(const int* __restrict__ src, const int* __restrict__ dst) {
    int i = blockIdx.x * blockDim.x + threadIdx.x;
    if (i >= EE) return;
    int s = src[i], d = dst[i];
    float e = g_asrc[s] + g_adst[d];
    e = e > 0.f ? e : 0.2f * e;     // leaky relu, slope 0.2
    g_e[i] = e;
    atomicMax(&g_m[d], enc_f(e));
}

// ---------------- edge pass B: exp + segment sum ----------------------------
__global__ void k_edgeB(const int* __restrict__ dst) {
    int i = blockIdx.x * blockDim.x + threadIdx.x;
    if (i >= EE) return;
    int d = dst[i];
    float m = dec_f(g_m[d]);
    float ee = expf(g_e[i] - m);
    g_e[i] = ee;
    atomicAdd(&g_denom[d], ee);
}

// ---------------- edge pass C: weighted scatter-add -------------------------
template <int C>
__global__ void k_edgeC(const int* __restrict__ src, const int* __restrict__ dst,
                        const float* __restrict__ H, float* __restrict__ Out) {
    constexpr int TPE = C / 4;  // threads per edge (32 or 16)
    long long g = (long long)blockIdx.x * blockDim.x + threadIdx.x;
    int e = (int)(g / TPE);
    if (e >= EE) return;
    int lane = (int)(g % TPE);
    int lt = threadIdx.x & 31;
    int leader = (lt / TPE) * TPE;

    int d = dst[e];
    float alpha = 0.f;
    if (lt == leader) alpha = g_e[e] / g_denom[d];
    alpha = __shfl_sync(0xffffffffu, alpha, leader);

    int s = src[e];
    float4 h = *(const float4*)&H[s * C + lane * 4];
    float* o = &Out[d * C + lane * 4];
    atomicAdd(o + 0, h.x * alpha);
    atomicAdd(o + 1, h.y * alpha);
    atomicAdd(o + 2, h.z * alpha);
    atomicAdd(o + 3, h.w * alpha);
}

// ---------------- bias (+ optional relu) ------------------------------------
template <int C, bool RELU>
__global__ void k_bias(float* __restrict__ A, const float* __restrict__ b, int n) {
    int i = blockIdx.x * blockDim.x + threadIdx.x;
    if (i >= n) return;
    float v = A[i] + b[i & (C - 1)];
    if (RELU) v = v > 0.f ? v : 0.f;
    A[i] = v;
}

// ---------------- launch ----------------------------------------------------
extern "C" void kernel_launch(void* const* d_in, const int* in_sizes, int n_in,
                              void* d_out, int out_size) {
    const float* x    = (const float*)d_in[0];
    const int*   ei   = (const int*)d_in[1];
    const float* Ws1  = (const float*)d_in[2];
    const float* Wd1  = (const float*)d_in[3];
    const float* as1  = (const float*)d_in[4];
    const float* ad1  = (const float*)d_in[5];
    const float* b1   = (const float*)d_in[6];
    const float* Ws2  = (const float*)d_in[7];
    const float* Wd2  = (const float*)d_in[8];
    const float* as2  = (const float*)d_in[9];
    const float* ad2  = (const float*)d_in[10];
    const float* b2   = (const float*)d_in[11];
    float* out = (float*)d_out;

    const int* src = ei;
    const int* dst = ei + EE;

    float *p_h1, *p_agg1, *p_h2;
    cudaGetSymbolAddress((void**)&p_h1, g_h1);
    cudaGetSymbolAddress((void**)&p_agg1, g_agg1);
    cudaGetSymbolAddress((void**)&p_h2, g_h2);

    const int TB = 256;
    const int edge_blocks = (EE + TB - 1) / TB;

    // ---------- layer 1 ----------
    k_wa<<<1, 128>>>(Ws1, as1, Wd1, ad1, HID);
    k_gemm<HID><<<NN / 32, HID>>>(x, Ws1, p_h1);
    {
        int n_agg = NN * HID;
        k_init<<<(n_agg + TB - 1) / TB, TB>>>(p_agg1, n_agg);
    }
    k_edgeA<<<edge_blocks, TB>>>(src, dst);
    k_edgeB<<<edge_blocks, TB>>>(dst);
    {
        long long tot = (long long)EE * (HID / 4);
        k_edgeC<HID><<<(int)((tot + TB - 1) / TB), TB>>>(src, dst, p_h1, p_agg1);
    }
    k_bias<HID, true><<<(NN * HID + TB - 1) / TB, TB>>>(p_agg1, b1, NN * HID);

    // ---------- layer 2 ----------
    k_wa<<<1, 128>>>(Ws2, as2, Wd2, ad2, OUTC);
    k_gemm<OUTC><<<NN / 32, OUTC>>>(p_agg1, Ws2, p_h2);
    {
        int n_agg = NN * OUTC;
        k_init<<<(n_agg + TB - 1) / TB, TB>>>(out, n_agg);
    }
    k_edgeA<<<edge_blocks, TB>>>(src, dst);
    k_edgeB<<<edge_blocks, TB>>>(dst);
    {
        long long tot = (long long)EE * (OUTC / 4);
        k_edgeC<OUTC><<<(int)((tot + TB - 1) / TB), TB>>>(src, dst, p_h2, out);
    }
    k_bias<OUTC, false><<<(NN * OUTC + TB - 1) / TB, TB>>>(out, b2, NN * OUTC);
}

// round 2
// speedup vs baseline: 2.5700x; 2.5700x over previous
#include <cuda_runtime.h>
#include <cuda_bf16.h>

// Problem constants (fixed shapes from reference setup_inputs)
constexpr int NN  = 100000;   // nodes
constexpr int EE  = 1600000;  // edges
constexpr int HID = 128;
constexpr int OUTC = 64;

constexpr int SCAN_B = 1024;
constexpr int NPART  = (NN + SCAN_B - 1) / SCAN_B;   // 98

// ---------------- scratch (static device globals; allocation-free) ----------
__device__ float g_h1[NN * HID];    // x @ W_src1
__device__ float g_agg1[NN * HID];  // layer1 output (bias+relu applied)
__device__ float g_h2[NN * OUTC];   // relu(agg1) @ W_src2
__device__ float g_asrc[NN];
__device__ float g_adst[NN];
__device__ float g_wa[2 * 128];     // [wa_src | wa_dst] for current layer

__device__ int   g_cnt[NN];         // histogram, then scatter cursor
__device__ int   g_off[NN + 1];     // CSR offsets by destination
__device__ int   g_part[NPART];     // scan partials
__device__ int   g_csrc[EE];        // source node of each dst-sorted edge

// ---------------- wa = W @ att (both src and dst), 128 outputs --------------
__global__ void k_wa(const float* __restrict__ Wsrc, const float* __restrict__ asrc,
                     const float* __restrict__ Wdst, const float* __restrict__ adst,
                     int cols) {
    int k = threadIdx.x;  // 128 threads, one per input-feature row of W
    float s1 = 0.f, s2 = 0.f;
    for (int j = 0; j < cols; j++) {
        s1 += Wsrc[k * cols + j] * asrc[j];
        s2 += Wdst[k * cols + j] * adst[j];
    }
    g_wa[k]       = s1;
    g_wa[128 + k] = s2;
}

// ---------------- GEMM: Y[N,COLS] = X[N,128] @ W[128,COLS] ------------------
// Also computes per-row dots with g_wa (a_src / a_dst) from the smem tile.
template <int COLS>
__global__ __launch_bounds__(COLS) void k_gemm(const float* __restrict__ X,
                                               const float* __restrict__ W,
                                               float* __restrict__ Y) {
    constexpr int RPB = 32;   // rows per block
    constexpr int KP  = 36;   // padded row stride for transposed tile
    __shared__ float xs[128 * KP];  // xs[k*KP + r]

    const int row0 = blockIdx.x * RPB;
    const int t = threadIdx.x;

    for (int idx = t; idx < RPB * 128; idx += COLS) {
        int r = idx >> 7;
        int k = idx & 127;
        xs[k * KP + r] = X[(row0 + r) * 128 + k];
    }
    __syncthreads();

    float acc[RPB];
#pragma unroll
    for (int r = 0; r < RPB; r++) acc[r] = 0.f;

#pragma unroll 4
    for (int k = 0; k < 128; k++) {
        float w = W[k * COLS + t];
        const float4* xp = (const float4*)&xs[k * KP];
#pragma unroll
        for (int rq = 0; rq < RPB / 4; rq++) {
            float4 xv = xp[rq];
            acc[rq * 4 + 0] += xv.x * w;
            acc[rq * 4 + 1] += xv.y * w;
            acc[rq * 4 + 2] += xv.z * w;
            acc[rq * 4 + 3] += xv.w * w;
        }
    }
#pragma unroll
    for (int r = 0; r < RPB; r++) Y[(row0 + r) * COLS + t] = acc[r];

    // per-row attention scalars from the same tile
    constexpr int TPR = COLS / 32;      // threads per row (4 or 2)
    constexpr int KSEG = 128 / TPR;
    int r = t / TPR, q = t % TPR;
    int k0 = q * KSEG;
    float s1 = 0.f, s2 = 0.f;
    for (int k = k0; k < k0 + KSEG; k++) {
        float xv = xs[k * KP + r];
        s1 += xv * g_wa[k];
        s2 += xv * g_wa[128 + k];
    }
#pragma unroll
    for (int off = TPR / 2; off > 0; off >>= 1) {
        s1 += __shfl_xor_sync(0xffffffffu, s1, off);
        s2 += __shfl_xor_sync(0xffffffffu, s2, off);
    }
    if (q == 0) {
        g_asrc[row0 + r] = s1;
        g_adst[row0 + r] = s2;
    }
}

// ======================= CSR build (by destination) =========================
__global__ void k_zero_cnt() {
    int i = blockIdx.x * blockDim.x + threadIdx.x;
    if (i < NN) g_cnt[i] = 0;
}

__global__ void k_hist(const int* __restrict__ dst) {
    int i = blockIdx.x * blockDim.x + threadIdx.x;
    if (i < EE) atomicAdd(&g_cnt[dst[i]], 1);
}

// block-wise exclusive scan (Hillis-Steele inclusive in smem, minus self)
__global__ __launch_bounds__(SCAN_B) void k_scan1() {
    __shared__ int sh[SCAN_B];
    int i = blockIdx.x * SCAN_B + threadIdx.x;
    int v = (i < NN) ? g_cnt[i] : 0;
    sh[threadIdx.x] = v;
    __syncthreads();
#pragma unroll
    for (int d = 1; d < SCAN_B; d <<= 1) {
        int t = (threadIdx.x >= d) ? sh[threadIdx.x - d] : 0;
        __syncthreads();
        sh[threadIdx.x] += t;
        __syncthreads();
    }
    if (i < NN) g_off[i] = sh[threadIdx.x] - v;   // exclusive within block
    if (threadIdx.x == SCAN_B - 1) g_part[blockIdx.x] = sh[SCAN_B - 1];
}

__global__ void k_scan2() {
    // tiny serial exclusive scan of NPART partials
    if (threadIdx.x == 0) {
        int run = 0;
        for (int b = 0; b < NPART; b++) {
            int v = g_part[b];
            g_part[b] = run;
            run += v;
        }
    }
}

__global__ __launch_bounds__(SCAN_B) void k_scan3() {
    int i = blockIdx.x * SCAN_B + threadIdx.x;
    if (i < NN) {
        g_off[i] += g_part[blockIdx.x];
        g_cnt[i] = 0;                 // reset cursor for scatter
    }
    if (i == 0) g_off[NN] = EE;
}

__global__ void k_scatter(const int* __restrict__ src, const int* __restrict__ dst) {
    int i = blockIdx.x * blockDim.x + threadIdx.x;
    if (i >= EE) return;
    int d = dst[i];
    int pos = g_off[d] + atomicAdd(&g_cnt[d], 1);
    g_csrc[pos] = src[i];
}

// =================== fused per-node softmax + aggregation ===================
// One warp per destination node. No atomics, no edge scratch.
template <int C, bool RELU>
__global__ __launch_bounds__(256) void k_agg(const float* __restrict__ H,
                                             const float* __restrict__ bias,
                                             float* __restrict__ Out) {
    constexpr int VL = C / 32;        // floats per lane (4 or 2)
    int warp = threadIdx.x >> 5;
    int lane = threadIdx.x & 31;
    int n = blockIdx.x * 8 + warp;
    if (n >= NN) return;

    int beg = g_off[n];
    int end = g_off[n + 1];
    float ad = g_adst[n];

    // ---- pass 1: warp-parallel max over incoming logits ----
    float m = -1e30f;
    for (int j = beg + lane; j < end; j += 32) {
        int s = g_csrc[j];
        float e = g_asrc[s] + ad;
        e = e > 0.f ? e : 0.2f * e;
        m = fmaxf(m, e);
    }
#pragma unroll
    for (int o = 16; o > 0; o >>= 1)
        m = fmaxf(m, __shfl_xor_sync(0xffffffffu, m, o));

    // ---- pass 2: exp weights + coalesced gather-accumulate ----
    float acc[VL];
#pragma unroll
    for (int v = 0; v < VL; v++) acc[v] = 0.f;
    float denom = 0.f;

    for (int j0 = beg; j0 < end; j0 += 32) {
        int j = j0 + lane;
        int s = 0;
        float w = 0.f;
        if (j < end) {
            s = g_csrc[j];
            float e = g_asrc[s] + ad;
            e = e > 0.f ? e : 0.2f * e;
            w = __expf(e - m);
        }
        denom += w;
        int cnt = min(32, end - j0);
        for (int k = 0; k < cnt; k++) {
            float wk = __shfl_sync(0xffffffffu, w, k);
            int   sk = __shfl_sync(0xffffffffu, s, k);
            if (C == 128) {
                float4 h = *(const float4*)&H[sk * 128 + lane * 4];
                acc[0] += wk * h.x;
                acc[1] += wk * h.y;
                acc[2] += wk * h.z;
                acc[3] += wk * h.w;
            } else {
                float2 h = *(const float2*)&H[sk * 64 + lane * 2];
                acc[0] += wk * h.x;
                acc[1] += wk * h.y;
            }
        }
    }
#pragma unroll
    for (int o = 16; o > 0; o >>= 1)
        denom += __shfl_xor_sync(0xffffffffu, denom, o);
    float inv = (end > beg) ? __frcp_rn(denom) : 0.f;

    if (C == 128) {
        float4 b4 = *(const float4*)&bias[lane * 4];
        float4 v;
        v.x = acc[0] * inv + b4.x;
        v.y = acc[1] * inv + b4.y;
        v.z = acc[2] * inv + b4.z;
        v.w = acc[3] * inv + b4.w;
        if (RELU) {
            v.x = fmaxf(v.x, 0.f); v.y = fmaxf(v.y, 0.f);
            v.z = fmaxf(v.z, 0.f); v.w = fmaxf(v.w, 0.f);
        }
        *(float4*)&Out[n * 128 + lane * 4] = v;
    } else {
        float2 b2 = *(const float2*)&bias[lane * 2];
        float2 v;
        v.x = acc[0] * inv + b2.x;
        v.y = acc[1] * inv + b2.y;
        if (RELU) { v.x = fmaxf(v.x, 0.f); v.y = fmaxf(v.y, 0.f); }
        *(float2*)&Out[n * 64 + lane * 2] = v;
    }
}

// ---------------- launch ----------------------------------------------------
extern "C" void kernel_launch(void* const* d_in, const int* in_sizes, int n_in,
                              void* d_out, int out_size) {
    const float* x    = (const float*)d_in[0];
    const int*   ei   = (const int*)d_in[1];
    const float* Ws1  = (const float*)d_in[2];
    const float* Wd1  = (const float*)d_in[3];
    const float* as1  = (const float*)d_in[4];
    const float* ad1  = (const float*)d_in[5];
    const float* b1   = (const float*)d_in[6];
    const float* Ws2  = (const float*)d_in[7];
    const float* Wd2  = (const float*)d_in[8];
    const float* as2  = (const float*)d_in[9];
    const float* ad2  = (const float*)d_in[10];
    const float* b2   = (const float*)d_in[11];
    float* out = (float*)d_out;

    const int* src = ei;
    const int* dst = ei + EE;

    float *p_h1, *p_agg1, *p_h2;
    cudaGetSymbolAddress((void**)&p_h1, g_h1);
    cudaGetSymbolAddress((void**)&p_agg1, g_agg1);
    cudaGetSymbolAddress((void**)&p_h2, g_h2);

    const int TB = 256;
    const int edge_blocks = (EE + TB - 1) / TB;
    const int node_blocks = (NN + TB - 1) / TB;
    const int agg_blocks  = (NN + 7) / 8;

    // ---------- CSR build (shared by both layers) ----------
    k_zero_cnt<<<node_blocks, TB>>>();
    k_hist<<<edge_blocks, TB>>>(dst);
    k_scan1<<<NPART, SCAN_B>>>();
    k_scan2<<<1, 32>>>();
    k_scan3<<<NPART, SCAN_B>>>();
    k_scatter<<<edge_blocks, TB>>>(src, dst);

    // ---------- layer 1 ----------
    k_wa<<<1, 128>>>(Ws1, as1, Wd1, ad1, HID);
    k_gemm<HID><<<NN / 32, HID>>>(x, Ws1, p_h1);
    k_agg<HID, true><<<agg_blocks, TB>>>(p_h1, b1, p_agg1);

    // ---------- layer 2 ----------
    k_wa<<<1, 128>>>(Ws2, as2, Wd2, ad2, OUTC);
    k_gemm<OUTC><<<NN / 32, OUTC>>>(p_agg1, Ws2, p_h2);
    k_agg<OUTC, false><<<agg_blocks, TB>>>(p_h2, b2, out);
}